// round 4
// baseline (speedup 1.0000x reference)
#include <cuda_runtime.h>
#include <math.h>

#define NU_ 200000
#define NI_ 100000
#define NG_ 50000
#define B_  65536
#define D_  256

// Scratch (static device globals -- no allocation APIs).
__device__ float g_up[NU_ * 16];   // user attention partials
__device__ float g_ia[NI_ * 16];   // item attention partials
__device__ float g_ip[NI_ * 8];    // item prediction partials

// ---------------------------------------------------------------------------
// Kernel A: up[u][f] = sum_d user_emb[u][d] * att_w1[d][f]   (d < 256, f < 16)
// Register-blocked: warp tile = 32 users x 16 f, lane = (ug 0..7, fg 0..3),
// each lane owns acc[4 users][4 f]. a-values via per-lane scalar-broadcast
// global loads (L1 resident within tile), b via conflict-free LDS.128.
// ---------------------------------------------------------------------------
__global__ __launch_bounds__(128) void user_pre(const float* __restrict__ ue,
                                                const float* __restrict__ aw1) {
    __shared__ float Ws[256 * 16];
    for (int idx = threadIdx.x; idx < 256 * 16; idx += 128) Ws[idx] = aw1[idx];
    __syncthreads();

    int warp = threadIdx.x >> 5, lane = threadIdx.x & 31;
    int tile = blockIdx.x * 4 + warp;
    if (tile * 32 >= NU_) return;

    int ug = lane >> 2, fg = lane & 3;
    int u0 = tile * 32 + ug * 4;
    const float* r0 = ue + (size_t)u0 * D_;

    float acc[4][4];
#pragma unroll
    for (int i = 0; i < 4; i++)
#pragma unroll
        for (int j = 0; j < 4; j++) acc[i][j] = 0.f;

    for (int q = 0; q < 64; q++) {
        float4 x[4];
#pragma unroll
        for (int i = 0; i < 4; i++)
            x[i] = *(const float4*)(r0 + i * D_ + q * 4);
#pragma unroll
        for (int dd = 0; dd < 4; dd++) {
            float4 bw = *(const float4*)&Ws[(q * 4 + dd) * 16 + fg * 4];
            float bj[4] = {bw.x, bw.y, bw.z, bw.w};
#pragma unroll
            for (int i = 0; i < 4; i++) {
                float xv = (dd == 0) ? x[i].x : (dd == 1) ? x[i].y
                          : (dd == 2) ? x[i].z : x[i].w;
#pragma unroll
                for (int j = 0; j < 4; j++)
                    acc[i][j] = fmaf(xv, bj[j], acc[i][j]);
            }
        }
    }
#pragma unroll
    for (int i = 0; i < 4; i++)
#pragma unroll
        for (int j = 0; j < 4; j++)
            g_up[(u0 + i) * 16 + fg * 4 + j] = acc[i][j];
}

// ---------------------------------------------------------------------------
// Kernel B: fused item partials. 24 outputs per item:
//   f in [0,16):  ia[i][f]   = sum_d item_emb[i][d] * att_w1[256+d][f]
//   f in [16,24): ip[i][f-16]= sum_d item_emb[i][d] * pred_w1[512+d][f-16]
// Warp tile = 32 items x 24 f, lane owns acc[4 items][6 f] (f = fg*6+m).
// ---------------------------------------------------------------------------
__global__ __launch_bounds__(128) void item_pre(const float* __restrict__ ie,
                                                const float* __restrict__ aw1,
                                                const float* __restrict__ pw1) {
    __shared__ float Ws[256 * 24];
    for (int idx = threadIdx.x; idx < 256 * 24; idx += 128) {
        int d = idx / 24, f = idx % 24;
        Ws[idx] = (f < 16) ? aw1[(256 + d) * 16 + f]
                           : pw1[(512 + d) * 8 + (f - 16)];
    }
    __syncthreads();

    int warp = threadIdx.x >> 5, lane = threadIdx.x & 31;
    int tile = blockIdx.x * 4 + warp;
    if (tile * 32 >= NI_) return;

    int ug = lane >> 2, fg = lane & 3;
    int i0 = tile * 32 + ug * 4;
    const float* r0 = ie + (size_t)i0 * D_;

    float acc[4][6];
#pragma unroll
    for (int i = 0; i < 4; i++)
#pragma unroll
        for (int m = 0; m < 6; m++) acc[i][m] = 0.f;

    for (int q = 0; q < 64; q++) {
        float4 x[4];
#pragma unroll
        for (int i = 0; i < 4; i++)
            x[i] = *(const float4*)(r0 + i * D_ + q * 4);
#pragma unroll
        for (int dd = 0; dd < 4; dd++) {
            const float* wr = &Ws[(q * 4 + dd) * 24 + fg * 6];
            float2 b0 = *(const float2*)(wr + 0);
            float2 b1 = *(const float2*)(wr + 2);
            float2 b2 = *(const float2*)(wr + 4);
            float bj[6] = {b0.x, b0.y, b1.x, b1.y, b2.x, b2.y};
#pragma unroll
            for (int i = 0; i < 4; i++) {
                float xv = (dd == 0) ? x[i].x : (dd == 1) ? x[i].y
                          : (dd == 2) ? x[i].z : x[i].w;
#pragma unroll
                for (int m = 0; m < 6; m++)
                    acc[i][m] = fmaf(xv, bj[m], acc[i][m]);
            }
        }
    }
#pragma unroll
    for (int i = 0; i < 4; i++)
#pragma unroll
        for (int m = 0; m < 6; m++) {
            int f = fg * 6 + m;
            int it = i0 + i;
            if (f < 16) g_ia[it * 16 + f] = acc[i][m];
            else        g_ip[it * 8 + (f - 16)] = acc[i][m];
        }
}

// ---------------------------------------------------------------------------
// Main kernel: one warp per batch element. Lane owns d = lane*8 .. lane*8+7.
// Pred weights staged in smem in permuted order (w = k*32+lane <-> d =
// lane*8+k) with (Wa,Wb) interleaved as float2 -> conflict-free LDS.64.
// ---------------------------------------------------------------------------
__global__ __launch_bounds__(256) void agree_main(
    const int*   __restrict__ gidx, const int*   __restrict__ iidx,
    const int*   __restrict__ gmem, const float* __restrict__ ue,
    const float* __restrict__ ie,   const float* __restrict__ ge,
    const float* __restrict__ ab1,  const float* __restrict__ aw2,
    const float* __restrict__ ab2,  const float* __restrict__ cw,
    const float* __restrict__ cb,   const float* __restrict__ pw1,
    const float* __restrict__ pb1,  const float* __restrict__ pw2,
    const float* __restrict__ pb2,  float* __restrict__ out) {
    __shared__ float Wab[8 * 256 * 2];  // [j][w][{Wa,Wb}], w permuted
    for (int idx = threadIdx.x; idx < 4096; idx += 256) {
        int j = idx >> 9;
        int w = (idx >> 1) & 255;
        int c = idx & 1;
        int d = (w & 31) * 8 + (w >> 5);
        Wab[idx] = c ? pw1[(256 + d) * 8 + j] : pw1[d * 8 + j];
    }
    __syncthreads();

    int b = blockIdx.x * 8 + (threadIdx.x >> 5);
    int lane = threadIdx.x & 31;

    int gid = gidx[b];
    int iid = iidx[b];
    int m[4];
#pragma unroll
    for (int s = 0; s < 4; s++) m[s] = gmem[gid * 4 + s];

    // ---- attention: h_s[f] = relu(up[m_s][f] + ia[i][f] + b1[f]) ----
    int f = lane & 15;
    float base = g_ia[iid * 16 + f] + ab1[f];
    float w2v = aw2[f];
    float part[4];
#pragma unroll
    for (int s = 0; s < 4; s++) {
        float hv = fmaxf(g_up[m[s] * 16 + f] + base, 0.f);
        part[s] = (lane < 16) ? hv * w2v : 0.f;
    }
    float ab2v = ab2[0];
    float lg[4];
#pragma unroll
    for (int s = 0; s < 4; s++) {
        float v = part[s];
#pragma unroll
        for (int mm = 16; mm > 0; mm >>= 1)
            v += __shfl_xor_sync(0xffffffffu, v, mm);
        lg[s] = v + ab2v;
    }

    // ---- softmax over 4 members (all lanes redundant) ----
    float mx = fmaxf(fmaxf(lg[0], lg[1]), fmaxf(lg[2], lg[3]));
    float ew[4], ssum = 0.f;
#pragma unroll
    for (int s = 0; s < 4; s++) { ew[s] = expf(lg[s] - mx); ssum += ew[s]; }
    float inv = 1.f / ssum;
    float at[4];
#pragma unroll
    for (int s = 0; s < 4; s++) at[s] = ew[s] * inv;

    if (lane < 4) out[B_ + b * 4 + lane] = at[lane];   // at_wt output

    // first-index argmax (strict >)
    int mi = 0;
    float bestv = at[0];
#pragma unroll
    for (int s = 1; s < 4; s++)
        if (at[s] > bestv) { bestv = at[s]; mi = s; }

    // classifier on the max-weight member (argmax over 2, ties -> class 0)
    float s0 = fmaf(bestv, cw[0], cb[0]);
    float s1 = fmaf(bestv, cw[1], cb[1]);
    int pc = (s1 > s0) ? 1 : 0;
    if (lane == 0) out[5 * B_ + b] = (float)pc;        // pred_class output

    // leader vs weighted-sum, expressed as one-hot / softmax weights
    float wsv[4];
#pragma unroll
    for (int s = 0; s < 4; s++)
        wsv[s] = pc ? ((s == mi) ? 1.f : 0.f) : at[s];

    // ---- gather rows, build g and item vectors (8 d's per lane) ----
    float gv[8], iv[8];
    {
        const float4* pg = (const float4*)ge + (size_t)gid * 64 + lane * 2;
        float4 a = pg[0], c4 = pg[1];
        gv[0] = a.x; gv[1] = a.y; gv[2] = a.z; gv[3] = a.w;
        gv[4] = c4.x; gv[5] = c4.y; gv[6] = c4.z; gv[7] = c4.w;
        const float4* pi = (const float4*)ie + (size_t)iid * 64 + lane * 2;
        float4 ai = pi[0], bi = pi[1];
        iv[0] = ai.x; iv[1] = ai.y; iv[2] = ai.z; iv[3] = ai.w;
        iv[4] = bi.x; iv[5] = bi.y; iv[6] = bi.z; iv[7] = bi.w;
#pragma unroll
        for (int s = 0; s < 4; s++) {
            const float4* pm = (const float4*)ue + (size_t)m[s] * 64 + lane * 2;
            float4 ma = pm[0], mb = pm[1];
            float w = wsv[s];
            gv[0] = fmaf(w, ma.x, gv[0]); gv[1] = fmaf(w, ma.y, gv[1]);
            gv[2] = fmaf(w, ma.z, gv[2]); gv[3] = fmaf(w, ma.w, gv[3]);
            gv[4] = fmaf(w, mb.x, gv[4]); gv[5] = fmaf(w, mb.y, gv[5]);
            gv[6] = fmaf(w, mb.z, gv[6]); gv[7] = fmaf(w, mb.w, gv[7]);
        }
    }

    // ---- prediction MLP partials: acc[j] += (g*i)*Wa[d][j] + g*Wb[d][j] ----
    float acc[8];
#pragma unroll
    for (int j = 0; j < 8; j++) acc[j] = 0.f;
#pragma unroll
    for (int k = 0; k < 8; k++) {
        float g1 = gv[k];
        float u1 = g1 * iv[k];
        int wbase = (k * 32 + lane) * 2;
#pragma unroll
        for (int j = 0; j < 8; j++) {
            float2 wv = *(const float2*)&Wab[j * 512 + wbase];
            acc[j] = fmaf(u1, wv.x, fmaf(g1, wv.y, acc[j]));
        }
    }
#pragma unroll
    for (int j = 0; j < 8; j++) {
        float v = acc[j];
#pragma unroll
        for (int mm = 16; mm > 0; mm >>= 1)
            v += __shfl_xor_sync(0xffffffffu, v, mm);
        acc[j] = v;
    }

    float z = 0.f;
#pragma unroll
    for (int j = 0; j < 8; j++) {
        float hid = fmaxf(acc[j] + g_ip[iid * 8 + j] + pb1[j], 0.f);
        z = fmaf(hid, pw2[j], z);
    }
    float y = 1.f / (1.f + expf(-(z + pb2[0])));
    if (lane == 0) out[b] = y;                         // y output
}

// ---------------------------------------------------------------------------
extern "C" void kernel_launch(void* const* d_in, const int* in_sizes, int n_in,
                              void* d_out, int out_size) {
    const int*   gidx = (const int*)d_in[0];
    const int*   iidx = (const int*)d_in[1];
    const int*   gmem = (const int*)d_in[2];
    const float* ue   = (const float*)d_in[3];
    const float* ie   = (const float*)d_in[4];
    const float* ge   = (const float*)d_in[5];
    const float* aw1  = (const float*)d_in[6];
    const float* ab1  = (const float*)d_in[7];
    const float* aw2  = (const float*)d_in[8];
    const float* ab2  = (const float*)d_in[9];
    const float* cw   = (const float*)d_in[10];
    const float* cb   = (const float*)d_in[11];
    const float* pw1  = (const float*)d_in[12];
    const float* pb1  = (const float*)d_in[13];
    const float* pw2  = (const float*)d_in[14];
    const float* pb2  = (const float*)d_in[15];
    float* out = (float*)d_out;

    user_pre<<<1563, 128>>>(ue, aw1);                 // 6250 warp tiles
    item_pre<<<782, 128>>>(ie, aw1, pw1);             // 3125 warp tiles
    agree_main<<<B_ / 8, 256>>>(gidx, iidx, gmem, ue, ie, ge,
                                ab1, aw2, ab2, cw, cb,
                                pw1, pb1, pw2, pb2, out);
}

// round 5
// speedup vs baseline: 1.6028x; 1.6028x over previous
#include <cuda_runtime.h>
#include <math.h>

#define NU_ 200000
#define NI_ 100000
#define NG_ 50000
#define B_  65536
#define D_  256

// Scratch (static device globals -- no allocation APIs).
__device__ float g_up[NU_ * 16];                 // user attention partials
__device__ float g_ia[NI_ * 16];                 // item attention partials
__device__ float g_ip[NI_ * 8];                  // item prediction partials
__device__ __align__(16) float g_wab[4096];      // permuted pred-MLP weights

// ---------------------------------------------------------------------------
// Tiny setup: permuted (Wa,Wb)-interleaved pred weights.
// Lane-owned d order in main kernel: k<4 -> d = lane*4+k ; k>=4 -> d = 128+lane*4+(k-4).
// g_wab[j*512 + (k*32+lane)*2 + {0,1}] = {pw1[d][j], pw1[256+d][j]}
// ---------------------------------------------------------------------------
__global__ void wab_pre(const float* __restrict__ pw1) {
    int idx = blockIdx.x * 256 + threadIdx.x;   // 16 blocks x 256 = 4096
    int j = idx >> 9;
    int w = (idx >> 1) & 255;
    int c = idx & 1;
    int k = w >> 5, lane = w & 31;
    int d = (k < 4) ? (lane * 4 + k) : (128 + lane * 4 + (k - 4));
    g_wab[idx] = c ? pw1[(256 + d) * 8 + j] : pw1[d * 8 + j];
}

// ---------------------------------------------------------------------------
// Fused precompute: one warp = one 32-row tile. Warps [0,6250) do users
// (16 outputs), warps [6250,9375) do items (24 outputs: 16 att + 8 pred).
// Explicit next-q prefetch keeps 8 float4 LDGs in flight per warp.
// ---------------------------------------------------------------------------
__global__ __launch_bounds__(256) void pre_all(const float* __restrict__ ue,
                                               const float* __restrict__ ie,
                                               const float* __restrict__ aw1,
                                               const float* __restrict__ pw1) {
    __shared__ float Wu[256 * 16];
    __shared__ float Wi[256 * 24];
    for (int idx = threadIdx.x; idx < 256 * 16; idx += 256) Wu[idx] = aw1[idx];
    for (int idx = threadIdx.x; idx < 256 * 24; idx += 256) {
        int d = idx / 24, f = idx % 24;
        Wi[idx] = (f < 16) ? aw1[(256 + d) * 16 + f]
                           : pw1[(512 + d) * 8 + (f - 16)];
    }
    __syncthreads();

    int w = blockIdx.x * 8 + (threadIdx.x >> 5);
    if (w >= 9375) return;
    int lane = threadIdx.x & 31;
    int ug = lane >> 2, fg = lane & 3;

    if (w < 6250) {
        // ---- user tile: 32 users x 16 f ----
        int u0 = w * 32 + ug * 4;
        const float* r0 = ue + (size_t)u0 * D_;

        float acc[4][4];
#pragma unroll
        for (int i = 0; i < 4; i++)
#pragma unroll
            for (int j = 0; j < 4; j++) acc[i][j] = 0.f;

        float4 x[4];
#pragma unroll
        for (int i = 0; i < 4; i++) x[i] = *(const float4*)(r0 + i * D_);

#pragma unroll 2
        for (int q = 0; q < 64; q++) {
            float4 xn[4];
            if (q < 63) {
#pragma unroll
                for (int i = 0; i < 4; i++)
                    xn[i] = *(const float4*)(r0 + i * D_ + (q + 1) * 4);
            }
#pragma unroll
            for (int dd = 0; dd < 4; dd++) {
                float4 bw = *(const float4*)&Wu[(q * 4 + dd) * 16 + fg * 4];
                float bj[4] = {bw.x, bw.y, bw.z, bw.w};
#pragma unroll
                for (int i = 0; i < 4; i++) {
                    float xv = (dd == 0) ? x[i].x : (dd == 1) ? x[i].y
                              : (dd == 2) ? x[i].z : x[i].w;
#pragma unroll
                    for (int j = 0; j < 4; j++)
                        acc[i][j] = fmaf(xv, bj[j], acc[i][j]);
                }
            }
            if (q < 63) {
#pragma unroll
                for (int i = 0; i < 4; i++) x[i] = xn[i];
            }
        }
#pragma unroll
        for (int i = 0; i < 4; i++)
#pragma unroll
            for (int j = 0; j < 4; j++)
                g_up[(u0 + i) * 16 + fg * 4 + j] = acc[i][j];
    } else {
        // ---- item tile: 32 items x 24 f (f = fg*6 + m) ----
        int t = w - 6250;
        int i0 = t * 32 + ug * 4;
        const float* r0 = ie + (size_t)i0 * D_;

        float acc[4][6];
#pragma unroll
        for (int i = 0; i < 4; i++)
#pragma unroll
            for (int mm = 0; mm < 6; mm++) acc[i][mm] = 0.f;

        float4 x[4];
#pragma unroll
        for (int i = 0; i < 4; i++) x[i] = *(const float4*)(r0 + i * D_);

#pragma unroll 2
        for (int q = 0; q < 64; q++) {
            float4 xn[4];
            if (q < 63) {
#pragma unroll
                for (int i = 0; i < 4; i++)
                    xn[i] = *(const float4*)(r0 + i * D_ + (q + 1) * 4);
            }
#pragma unroll
            for (int dd = 0; dd < 4; dd++) {
                const float* wr = &Wi[(q * 4 + dd) * 24 + fg * 6];
                float2 b0 = *(const float2*)(wr + 0);
                float2 b1 = *(const float2*)(wr + 2);
                float2 b2 = *(const float2*)(wr + 4);
                float bj[6] = {b0.x, b0.y, b1.x, b1.y, b2.x, b2.y};
#pragma unroll
                for (int i = 0; i < 4; i++) {
                    float xv = (dd == 0) ? x[i].x : (dd == 1) ? x[i].y
                              : (dd == 2) ? x[i].z : x[i].w;
#pragma unroll
                    for (int mm = 0; mm < 6; mm++)
                        acc[i][mm] = fmaf(xv, bj[mm], acc[i][mm]);
                }
            }
            if (q < 63) {
#pragma unroll
                for (int i = 0; i < 4; i++) x[i] = xn[i];
            }
        }
#pragma unroll
        for (int i = 0; i < 4; i++)
#pragma unroll
            for (int mm = 0; mm < 6; mm++) {
                int f = fg * 6 + mm;
                int it = i0 + i;
                if (f < 16) g_ia[it * 16 + f] = acc[i][mm];
                else        g_ip[it * 8 + (f - 16)] = acc[i][mm];
            }
    }
}

// ---------------------------------------------------------------------------
// Main kernel: one warp per batch element, 8 warps/block.
// Lane owns d in {lane*4+r} U {128+lane*4+r}: all row loads are fully
// coalesced LDG.128 (512B/warp contiguous). All 12 heavy row loads are issued
// BEFORE attention math so DRAM latency hides under the scalar section.
// ---------------------------------------------------------------------------
__global__ __launch_bounds__(256) void agree_main(
    const int*   __restrict__ gidx, const int*   __restrict__ iidx,
    const int*   __restrict__ gmem, const float* __restrict__ ue,
    const float* __restrict__ ie,   const float* __restrict__ ge,
    const float* __restrict__ ab1,  const float* __restrict__ aw2,
    const float* __restrict__ ab2,  const float* __restrict__ cw,
    const float* __restrict__ cb,   const float* __restrict__ pb1,
    const float* __restrict__ pw2,  const float* __restrict__ pb2,
    float* __restrict__ out) {
    __shared__ __align__(16) float Wab[4096];
    {
        const float4* s4 = (const float4*)g_wab;
        float4* d4 = (float4*)Wab;
#pragma unroll
        for (int i = 0; i < 4; i++)
            d4[threadIdx.x + i * 256] = s4[threadIdx.x + i * 256];
    }
    __syncthreads();

    int b = blockIdx.x * 8 + (threadIdx.x >> 5);
    int lane = threadIdx.x & 31;

    int gid = gidx[b];
    int iid = iidx[b];
    int4 mv = ((const int4*)gmem)[gid];
    int m[4] = {mv.x, mv.y, mv.z, mv.w};

    // ---- issue all heavy row gathers up front (coalesced) ----
    const float* gr = ge + (size_t)gid * D_;
    const float* ir = ie + (size_t)iid * D_;
    float4 gA = *(const float4*)(gr + lane * 4);
    float4 gB = *(const float4*)(gr + 128 + lane * 4);
    float4 iA = *(const float4*)(ir + lane * 4);
    float4 iB = *(const float4*)(ir + 128 + lane * 4);
    float4 mA[4], mB[4];
#pragma unroll
    for (int s = 0; s < 4; s++) {
        const float* mr = ue + (size_t)m[s] * D_;
        mA[s] = *(const float4*)(mr + lane * 4);
        mB[s] = *(const float4*)(mr + 128 + lane * 4);
    }

    // ---- attention logits from precomputed partials ----
    int f = lane & 15;
    float base = g_ia[iid * 16 + f] + ab1[f];
    float w2v = aw2[f];
    float ab2v = ab2[0];
    float lg[4];
#pragma unroll
    for (int s = 0; s < 4; s++) {
        float hv = fmaxf(g_up[m[s] * 16 + f] + base, 0.f);
        float v = (lane < 16) ? hv * w2v : 0.f;
#pragma unroll
        for (int o = 16; o > 0; o >>= 1)
            v += __shfl_xor_sync(0xffffffffu, v, o);
        lg[s] = v + ab2v;
    }

    // ---- softmax (fast exp; argmax taken on logits -> rounding-immune) ----
    float mx = fmaxf(fmaxf(lg[0], lg[1]), fmaxf(lg[2], lg[3]));
    float ew[4], ssum = 0.f;
#pragma unroll
    for (int s = 0; s < 4; s++) { ew[s] = __expf(lg[s] - mx); ssum += ew[s]; }
    float inv = 1.f / ssum;
    float at[4];
#pragma unroll
    for (int s = 0; s < 4; s++) at[s] = ew[s] * inv;

    if (lane < 4) out[B_ + b * 4 + lane] = at[lane];   // at_wt output

    // first-index argmax (strict >) on logits == argmax on at_wt (monotone)
    int mi = 0; float blg = lg[0], bat = at[0];
#pragma unroll
    for (int s = 1; s < 4; s++)
        if (lg[s] > blg) { blg = lg[s]; mi = s; bat = at[s]; }

    // classifier on max-weight member (argmax over 2, tie -> class 0)
    float s0 = fmaf(bat, cw[0], cb[0]);
    float s1 = fmaf(bat, cw[1], cb[1]);
    int pc = (s1 > s0) ? 1 : 0;
    if (lane == 0) out[5 * B_ + b] = (float)pc;        // pred_class output

    float wsv[4];
#pragma unroll
    for (int s = 0; s < 4; s++)
        wsv[s] = pc ? ((s == mi) ? 1.f : 0.f) : at[s];

    // ---- g = group_emb + (leader | weighted member sum) ----
    float gv[8] = {gA.x, gA.y, gA.z, gA.w, gB.x, gB.y, gB.z, gB.w};
    float iv[8] = {iA.x, iA.y, iA.z, iA.w, iB.x, iB.y, iB.z, iB.w};
#pragma unroll
    for (int s = 0; s < 4; s++) {
        float ww = wsv[s];
        gv[0] = fmaf(ww, mA[s].x, gv[0]); gv[1] = fmaf(ww, mA[s].y, gv[1]);
        gv[2] = fmaf(ww, mA[s].z, gv[2]); gv[3] = fmaf(ww, mA[s].w, gv[3]);
        gv[4] = fmaf(ww, mB[s].x, gv[4]); gv[5] = fmaf(ww, mB[s].y, gv[5]);
        gv[6] = fmaf(ww, mB[s].z, gv[6]); gv[7] = fmaf(ww, mB[s].w, gv[7]);
    }

    // ---- prediction MLP: acc[j] += (g*i)*Wa[d][j] + g*Wb[d][j] ----
    float acc[8];
#pragma unroll
    for (int j = 0; j < 8; j++) acc[j] = 0.f;
#pragma unroll
    for (int k = 0; k < 8; k++) {
        float g1 = gv[k];
        float u1 = g1 * iv[k];
        int wbase = (k * 32 + lane) * 2;
#pragma unroll
        for (int j = 0; j < 8; j++) {
            float2 wv = *(const float2*)&Wab[j * 512 + wbase];
            acc[j] = fmaf(u1, wv.x, fmaf(g1, wv.y, acc[j]));
        }
    }
#pragma unroll
    for (int j = 0; j < 8; j++) {
        float v = acc[j];
#pragma unroll
        for (int o = 16; o > 0; o >>= 1)
            v += __shfl_xor_sync(0xffffffffu, v, o);
        acc[j] = v;
    }

    float4 ip0 = *(const float4*)&g_ip[iid * 8];
    float4 ip1 = *(const float4*)&g_ip[iid * 8 + 4];
    float4 b1a = *(const float4*)&pb1[0];
    float4 b1b = *(const float4*)&pb1[4];
    float4 w2a = *(const float4*)&pw2[0];
    float4 w2b = *(const float4*)&pw2[4];
    float ipv[8] = {ip0.x, ip0.y, ip0.z, ip0.w, ip1.x, ip1.y, ip1.z, ip1.w};
    float bv[8]  = {b1a.x, b1a.y, b1a.z, b1a.w, b1b.x, b1b.y, b1b.z, b1b.w};
    float wv2[8] = {w2a.x, w2a.y, w2a.z, w2a.w, w2b.x, w2b.y, w2b.z, w2b.w};

    float z = 0.f;
#pragma unroll
    for (int j = 0; j < 8; j++) {
        float hid = fmaxf(acc[j] + ipv[j] + bv[j], 0.f);
        z = fmaf(hid, wv2[j], z);
    }
    float y = 1.f / (1.f + __expf(-(z + pb2[0])));
    if (lane == 0) out[b] = y;                         // y output
}

// ---------------------------------------------------------------------------
extern "C" void kernel_launch(void* const* d_in, const int* in_sizes, int n_in,
                              void* d_out, int out_size) {
    const int*   gidx = (const int*)d_in[0];
    const int*   iidx = (const int*)d_in[1];
    const int*   gmem = (const int*)d_in[2];
    const float* ue   = (const float*)d_in[3];
    const float* ie   = (const float*)d_in[4];
    const float* ge   = (const float*)d_in[5];
    const float* aw1  = (const float*)d_in[6];
    const float* ab1  = (const float*)d_in[7];
    const float* aw2  = (const float*)d_in[8];
    const float* ab2  = (const float*)d_in[9];
    const float* cw   = (const float*)d_in[10];
    const float* cb   = (const float*)d_in[11];
    const float* pw1  = (const float*)d_in[12];
    const float* pb1  = (const float*)d_in[13];
    const float* pw2  = (const float*)d_in[14];
    const float* pb2  = (const float*)d_in[15];
    float* out = (float*)d_out;

    wab_pre<<<16, 256>>>(pw1);
    pre_all<<<1172, 256>>>(ue, ie, aw1, pw1);          // 9375 warp tiles
    agree_main<<<B_ / 8, 256>>>(gidx, iidx, gmem, ue, ie, ge,
                                ab1, aw2, ab2, cw, cb,
                                pb1, pw2, pb2, out);
}